// round 1
// baseline (speedup 1.0000x reference)
#include <cuda_runtime.h>
#include <math.h>
#include <stdint.h>

// Problem constants
constexpr int Bn = 4096;
constexpr int An = 32;
constexpr int Sn = 128;
constexpr int Hn = 128;
constexpr int G4 = 4 * Hn;          // 512
constexpr int M_BIG = Bn * An;      // 131072
constexpr int BAH = Bn * An * Hn;   // 16,777,216

// -------------------- scratch (__device__ globals; no allocs) --------------------
__device__ float g_buf1[BAH];              // enc, later x           (67 MB)
__device__ float g_buf2[(size_t)Bn * An * G4]; // gates, later y (first quarter) (268 MB)
__device__ float g_WeT[Sn * Hn];           // We^T  [s][h]
__device__ float g_WtT[Hn * Hn];           // Wt^T  [h][o]
__device__ float g_WihT[An * Hn * G4];     // W_ih^T per agent [a][h][g]  (8 MB)
__device__ float g_hh[An * G4];            // W_hh@h0 + b_ih + b_hh
__device__ unsigned long long g_argmax[An];

// -------------------- tiny prep kernels --------------------
__global__ void k_trans128(const float* __restrict__ in, float* __restrict__ out) {
    int idx = blockIdx.x * blockDim.x + threadIdx.x;   // 16384
    int r = idx >> 7, c = idx & 127;
    out[idx] = in[c * 128 + r];                        // out[r][c] = in[c][r]
}

__global__ void k_trans_wih(const float* __restrict__ in, float* __restrict__ out) {
    int idx = blockIdx.x * blockDim.x + threadIdx.x;   // 2,097,152
    int a = idx >> 16;
    int r = idx & 65535;
    int h = r >> 9;
    int g = r & 511;
    out[idx] = in[(a << 16) + (g << 7) + h];           // out[a][h][g] = in[a][g][h]
}

// hh[a][g] = sum_h h0[a][h]*W_hh[a][g][h] + b_ih[a][g] + b_hh[a][g]
__global__ void k_hh(const float* __restrict__ h0, const float* __restrict__ Whh,
                     const float* __restrict__ bih, const float* __restrict__ bhh) {
    int w = (blockIdx.x * blockDim.x + threadIdx.x) >> 5;  // 16384 warps
    int lane = threadIdx.x & 31;
    if (w >= An * G4) return;
    int a = w / G4;
    float4 hv = *reinterpret_cast<const float4*>(h0 + a * Hn + lane * 4);
    float4 wv = *reinterpret_cast<const float4*>(Whh + (size_t)w * Hn + lane * 4);
    float s = hv.x * wv.x + hv.y * wv.y + hv.z * wv.z + hv.w * wv.w;
    #pragma unroll
    for (int off = 16; off; off >>= 1) s += __shfl_xor_sync(0xFFFFFFFFu, s, off);
    if (lane == 0) g_hh[w] = s + bih[w] + bhh[w];
}

// -------------------- SGEMM 128x128 tile, BK=16, 8x8/thread --------------------
__global__ __launch_bounds__(256)
void sgemm_kernel(const float* __restrict__ Ain, const float* __restrict__ Bin,
                  float* __restrict__ Cout,
                  int K, int lda, int ldb, int ldc,
                  int a_zoff, int b_zoff, int c_zoff,
                  const float* __restrict__ bias, int bias_zoff,
                  const float* __restrict__ add, int add_ld)
{
    const int z = blockIdx.z;
    const float* Ap = Ain + (size_t)z * a_zoff;
    const float* Bp = Bin + (size_t)z * b_zoff;
    float* Cp = Cout + (size_t)z * c_zoff;
    const float* biasp = bias + (size_t)z * bias_zoff;

    __shared__ float As[16][128];
    __shared__ float Bs[16][128];

    const int tid = threadIdx.x;
    const int tx = tid & 15, ty = tid >> 4;
    const int m0 = blockIdx.x * 128;
    const int n0 = blockIdx.y * 128;

    float acc[8][8];
    #pragma unroll
    for (int i = 0; i < 8; i++)
        #pragma unroll
        for (int j = 0; j < 8; j++) acc[i][j] = 0.f;

    for (int k0 = 0; k0 < K; k0 += 16) {
        // A tile: 128 rows x 16 k  (store transposed As[k][m])
        #pragma unroll
        for (int jj = 0; jj < 2; jj++) {
            int lin = tid + jj * 256;          // float4 index, 512 total
            int row = lin >> 2;
            int c4 = lin & 3;
            float4 v = *reinterpret_cast<const float4*>(
                Ap + (size_t)(m0 + row) * lda + k0 + c4 * 4);
            As[c4 * 4 + 0][row] = v.x;
            As[c4 * 4 + 1][row] = v.y;
            As[c4 * 4 + 2][row] = v.z;
            As[c4 * 4 + 3][row] = v.w;
        }
        // B tile: 16 k x 128 n
        #pragma unroll
        for (int jj = 0; jj < 2; jj++) {
            int lin = tid + jj * 256;
            int kk = lin >> 5;
            int n4 = lin & 31;
            *reinterpret_cast<float4*>(&Bs[kk][n4 * 4]) =
                *reinterpret_cast<const float4*>(Bp + (size_t)(k0 + kk) * ldb + n0 + n4 * 4);
        }
        __syncthreads();
        #pragma unroll
        for (int k = 0; k < 16; k++) {
            float av[8], bv[8];
            *reinterpret_cast<float4*>(&av[0]) = *reinterpret_cast<float4*>(&As[k][ty * 8]);
            *reinterpret_cast<float4*>(&av[4]) = *reinterpret_cast<float4*>(&As[k][ty * 8 + 4]);
            *reinterpret_cast<float4*>(&bv[0]) = *reinterpret_cast<float4*>(&Bs[k][tx * 8]);
            *reinterpret_cast<float4*>(&bv[4]) = *reinterpret_cast<float4*>(&Bs[k][tx * 8 + 4]);
            #pragma unroll
            for (int i = 0; i < 8; i++)
                #pragma unroll
                for (int j = 0; j < 8; j++) acc[i][j] += av[i] * bv[j];
        }
        __syncthreads();
    }

    #pragma unroll
    for (int i = 0; i < 8; i++) {
        int m = m0 + ty * 8 + i;
        #pragma unroll
        for (int j = 0; j < 8; j += 4) {
            int n = n0 + tx * 8 + j;
            float4 v;
            v.x = acc[i][j + 0] + biasp[n + 0];
            v.y = acc[i][j + 1] + biasp[n + 1];
            v.z = acc[i][j + 2] + biasp[n + 2];
            v.w = acc[i][j + 3] + biasp[n + 3];
            if (add) {
                float4 av = *reinterpret_cast<const float4*>(add + (size_t)m * add_ld + n);
                v.x += av.x; v.y += av.y; v.z += av.z; v.w += av.w;
            }
            *reinterpret_cast<float4*>(Cp + (size_t)m * ldc + n) = v;
        }
    }
}

// -------------------- LSTM cell elementwise --------------------
__device__ __forceinline__ float sigf(float x) { return 1.0f / (1.0f + expf(-x)); }

__global__ void k_cell(const float* __restrict__ c0, float* __restrict__ dout) {
    int idx = blockIdx.x * blockDim.x + threadIdx.x;   // BAH
    int m = idx >> 7;        // pair (b*A+a)
    int h = idx & 127;
    int a = m & 31;
    size_t base = (size_t)m * G4;
    float ig = g_buf2[base + h];
    float fg = g_buf2[base + 128 + h];
    float gg = g_buf2[base + 256 + h];
    float og = g_buf2[base + 384 + h];
    float c1 = sigf(fg) * c0[a * Hn + h] + sigf(ig) * tanhf(gg);
    float h1 = sigf(og) * tanhf(c1);
    dout[BAH + idx] = h1;
    dout[2 * BAH + idx] = c1;
}

// -------------------- comm gate: probs + per-agent global argmax --------------------
__global__ void k_init_argmax() {
    if (threadIdx.x < An) g_argmax[threadIdx.x] = 0ull;
}

__global__ void k_argmax(const float* __restrict__ h1, const float* __restrict__ Wg,
                         const float* __restrict__ bg) {
    int w = (blockIdx.x * blockDim.x + threadIdx.x) >> 5;   // pair index b*A+a
    int lane = threadIdx.x & 31;
    if (w >= M_BIG) return;
    int b = w / An, a = w % An;
    float4 hv = *reinterpret_cast<const float4*>(h1 + (size_t)w * Hn + lane * 4);
    const float* wg = Wg + a * 2 * Hn;
    float4 g0 = *reinterpret_cast<const float4*>(wg + lane * 4);
    float4 g1 = *reinterpret_cast<const float4*>(wg + Hn + lane * 4);
    float l0 = hv.x * g0.x + hv.y * g0.y + hv.z * g0.z + hv.w * g0.w;
    float l1 = hv.x * g1.x + hv.y * g1.y + hv.z * g1.z + hv.w * g1.w;
    #pragma unroll
    for (int off = 16; off; off >>= 1) {
        l0 += __shfl_xor_sync(0xFFFFFFFFu, l0, off);
        l1 += __shfl_xor_sync(0xFFFFFFFFu, l1, off);
    }
    if (lane == 0) {
        l0 += bg[a * 2 + 0];
        l1 += bg[a * 2 + 1];
        float mm = fmaxf(l0, l1);
        float e0 = expf(l0 - mm), e1 = expf(l1 - mm);
        float s = e0 + e1;
        float p0 = e0 / s, p1 = e1 / s;
        float key; unsigned pidx;
        if (p0 >= p1) { key = p0; pidx = (unsigned)(2 * b); }
        else          { key = p1; pidx = (unsigned)(2 * b + 1); }
        // key in (0,1] -> positive float, bit pattern is order-preserving.
        // invert index so ties pick the LOWEST index (first occurrence, jnp.argmax).
        unsigned long long packed =
            ((unsigned long long)__float_as_uint(key) << 32) | (0xFFFFFFFFu - pidx);
        atomicMax(&g_argmax[a], packed);
    }
}

// -------------------- build x = comm_sum - idx*h1 --------------------
__global__ __launch_bounds__(256)
void k_build_x(const float* __restrict__ h1, float* __restrict__ x,
               const int* __restrict__ alive) {
    __shared__ float sh[An][Hn];
    __shared__ float sidx[An];
    __shared__ float scs[Hn];
    int b = blockIdx.x;
    int tid = threadIdx.x;
    const float* hp = h1 + (size_t)b * An * Hn;
    #pragma unroll
    for (int jj = 0; jj < 4; jj++) {
        int lin = tid + jj * 256;      // float4 index, 1024 total
        int a = lin >> 5, c4 = lin & 31;
        *reinterpret_cast<float4*>(&sh[a][c4 * 4]) =
            *reinterpret_cast<const float4*>(hp + (size_t)lin * 4);
    }
    if (tid < An)
        sidx[tid] = (float)(0xFFFFFFFFu - (unsigned)(g_argmax[tid] & 0xFFFFFFFFull));
    __syncthreads();
    if (tid < Hn) {
        int v = alive ? *alive : An;
        if (v < 0 || v > (1 << 20)) v = (int)__int_as_float(v);  // robustness if dtype is f32
        float norm = v ? 1.0f / (float)(v - 1) : 1.0f;
        float sum = 0.f;
        #pragma unroll
        for (int a = 0; a < An; a++) sum += sidx[a] * sh[a][tid];
        scs[tid] = norm * sum;
    }
    __syncthreads();
    float* xp = x + (size_t)b * An * Hn;
    #pragma unroll
    for (int jj = 0; jj < 4; jj++) {
        int lin = tid + jj * 256;
        int a = lin >> 5, c4 = lin & 31;
        float4 hv = *reinterpret_cast<float4*>(&sh[a][c4 * 4]);
        float ia = sidx[a];
        float4 o;
        o.x = scs[c4 * 4 + 0] - ia * hv.x;
        o.y = scs[c4 * 4 + 1] - ia * hv.y;
        o.z = scs[c4 * 4 + 2] - ia * hv.z;
        o.w = scs[c4 * 4 + 3] - ia * hv.w;
        *reinterpret_cast<float4*>(xp + (size_t)lin * 4) = o;
    }
}

// -------------------- row softmax (128 wide), warp per row --------------------
__global__ void k_softmax(const float* __restrict__ y, float* __restrict__ out) {
    int w = (blockIdx.x * blockDim.x + threadIdx.x) >> 5;
    int lane = threadIdx.x & 31;
    if (w >= M_BIG) return;
    const float* row = y + (size_t)w * Hn;
    float4 v = *reinterpret_cast<const float4*>(row + lane * 4);
    float mx = fmaxf(fmaxf(v.x, v.y), fmaxf(v.z, v.w));
    #pragma unroll
    for (int off = 16; off; off >>= 1) mx = fmaxf(mx, __shfl_xor_sync(0xFFFFFFFFu, mx, off));
    float4 e;
    e.x = expf(v.x - mx); e.y = expf(v.y - mx);
    e.z = expf(v.z - mx); e.w = expf(v.w - mx);
    float s = e.x + e.y + e.z + e.w;
    #pragma unroll
    for (int off = 16; off; off >>= 1) s += __shfl_xor_sync(0xFFFFFFFFu, s, off);
    float inv = 1.0f / s;
    e.x *= inv; e.y *= inv; e.z *= inv; e.w *= inv;
    *reinterpret_cast<float4*>(out + (size_t)w * Hn + lane * 4) = e;
}

// -------------------- launch --------------------
extern "C" void kernel_launch(void* const* d_in, const int* in_sizes, int n_in,
                              void* d_out, int out_size) {
    const float* obs = (const float*)d_in[0];
    const float* cv  = (const float*)d_in[1];
    const float* h0  = (const float*)d_in[2];
    const float* c0  = (const float*)d_in[3];
    const float* We  = (const float*)d_in[4];
    const float* be  = (const float*)d_in[5];
    const float* Wih = (const float*)d_in[6];
    const float* Whh = (const float*)d_in[7];
    const float* bih = (const float*)d_in[8];
    const float* bhh = (const float*)d_in[9];
    const float* Wg  = (const float*)d_in[10];
    const float* bg  = (const float*)d_in[11];
    const float* Wt  = (const float*)d_in[12];
    const float* bt  = (const float*)d_in[13];
    const int* alive = (n_in > 14) ? (const int*)d_in[14] : nullptr;
    float* dout = (float*)d_out;

    float *p_buf1, *p_buf2, *p_WeT, *p_WtT, *p_WihT, *p_hh;
    cudaGetSymbolAddress((void**)&p_buf1, g_buf1);
    cudaGetSymbolAddress((void**)&p_buf2, g_buf2);
    cudaGetSymbolAddress((void**)&p_WeT, g_WeT);
    cudaGetSymbolAddress((void**)&p_WtT, g_WtT);
    cudaGetSymbolAddress((void**)&p_WihT, g_WihT);
    cudaGetSymbolAddress((void**)&p_hh, g_hh);

    // prep
    k_trans128<<<64, 256>>>(We, p_WeT);
    k_trans128<<<64, 256>>>(Wt, p_WtT);
    k_trans_wih<<<8192, 256>>>(Wih, p_WihT);
    k_hh<<<2048, 256>>>(h0, Whh, bih, bhh);

    // enc = obs @ We^T + be + cv   -> g_buf1
    {
        dim3 grid(M_BIG / 128, 1, 1);
        sgemm_kernel<<<grid, 256>>>(obs, p_WeT, p_buf1,
                                    Sn, Sn, Hn, Hn,
                                    0, 0, 0,
                                    be, 0, cv, Hn);
    }
    // gates = enc @ W_ih^T + hh   (batched over agents) -> g_buf2
    {
        dim3 grid(Bn / 128, G4 / 128, An);
        sgemm_kernel<<<grid, 256>>>(p_buf1, p_WihT, p_buf2,
                                    Hn, An * Hn, G4, An * G4,
                                    Hn, Hn * G4, G4,
                                    p_hh, G4, nullptr, 0);
    }
    // LSTM cell -> h1, c1 written straight into d_out
    k_cell<<<BAH / 256, 256>>>(c0, dout);

    // comm gate argmax
    k_init_argmax<<<1, 32>>>();
    k_argmax<<<M_BIG / 8, 256>>>(dout + BAH, Wg, bg);

    // x = comm_sum - idx*h1 -> g_buf1 (reuses enc)
    k_build_x<<<Bn, 256>>>(dout + BAH, p_buf1, alive);

    // y = x @ Wt^T + bt -> g_buf2 (reuses gates)
    {
        dim3 grid(M_BIG / 128, 1, 1);
        sgemm_kernel<<<grid, 256>>>(p_buf1, p_WtT, p_buf2,
                                    Hn, Hn, Hn, Hn,
                                    0, 0, 0,
                                    bt, 0, nullptr, 0);
    }
    // out = softmax(y) -> d_out[0:BAH]
    k_softmax<<<M_BIG / 8, 256>>>(p_buf2, dout);
}

// round 3
// speedup vs baseline: 1.2178x; 1.2178x over previous
#include <cuda_runtime.h>
#include <math.h>
#include <stdint.h>

// Problem constants
constexpr int Bn = 4096;
constexpr int An = 32;
constexpr int Sn = 128;
constexpr int Hn = 128;
constexpr int G4 = 4 * Hn;          // 512
constexpr int M_BIG = Bn * An;      // 131072
constexpr int BAH = Bn * An * Hn;   // 16,777,216

// -------------------- scratch --------------------
__device__ float g_buf1[BAH];                  // enc, later x (67 MB)
__device__ float g_hh[An * G4];                // interleaved (4h+gate) hidden bias
__device__ unsigned long long g_argmax[An];

// -------------------- f32x2 helpers --------------------
__device__ __forceinline__ unsigned long long packf2(float x) {
    unsigned long long r;
    unsigned xi = __float_as_uint(x);
    asm("mov.b64 %0, {%1, %1};" : "=l"(r) : "r"(xi));
    return r;
}
__device__ __forceinline__ void fma2(unsigned long long& d,
                                     unsigned long long a, unsigned long long b) {
    asm("fma.rn.f32x2 %0, %1, %2, %0;" : "+l"(d) : "l"(a), "l"(b));
}
__device__ __forceinline__ float2 unpk(unsigned long long v) {
    float2 r;
    asm("mov.b64 {%0, %1}, %2;" : "=f"(r.x), "=f"(r.y) : "l"(v));
    return r;
}
__device__ __forceinline__ float sigf(float x) { return 1.0f / (1.0f + expf(-x)); }

// hh[a][4h+gate] = (W_hh@h0)[a][gate*128+h] + b_ih + b_hh  (interleaved)
__global__ void k_hh(const float* __restrict__ h0, const float* __restrict__ Whh,
                     const float* __restrict__ bih, const float* __restrict__ bhh) {
    int w = (blockIdx.x * blockDim.x + threadIdx.x) >> 5;  // 16384 warps
    int lane = threadIdx.x & 31;
    if (w >= An * G4) return;
    int a = w / G4;
    float4 hv = *reinterpret_cast<const float4*>(h0 + a * Hn + lane * 4);
    float4 wv = *reinterpret_cast<const float4*>(Whh + (size_t)w * Hn + lane * 4);
    float s = hv.x * wv.x + hv.y * wv.y + hv.z * wv.z + hv.w * wv.w;
    #pragma unroll
    for (int off = 16; off; off >>= 1) s += __shfl_xor_sync(0xFFFFFFFFu, s, off);
    if (lane == 0) {
        int gsrc = w % G4;
        int gate = gsrc >> 7, h = gsrc & 127;
        g_hh[a * G4 + 4 * h + gate] = s + bih[w] + bhh[w];
    }
}

// -------------------- fused f32x2 GEMM --------------------
// C[m][n] = sum_k A[m][k] * Bsrc[n][k]    (NT GEMM, B row-major [n][k], ldb=128)
// MODE 0: enc   = obs@We^T + be + cv              (A=obs, lda=128)
// MODE 1: gates = enc_a@Wih_a^T + hh_a -> LSTM cell -> h1, c1
//         (A=enc+z*128, lda=4096; B cols permuted n=4h+gate; z=agent)
// MODE 2: y = x@Wt^T + bt -> row softmax -> out   (A=x, lda=128, gridDim.y=1)
template <int MODE>
__global__ __launch_bounds__(256, 2)
void gemm_k(const float* __restrict__ A, const float* __restrict__ Bsrc,
            float* __restrict__ C, int lda,
            const float* __restrict__ bias,
            const float* __restrict__ extra,   // MODE0: cv  MODE1: c0
            float* __restrict__ out2)          // MODE1: c1
{
    __shared__ __align__(16) float As[16][132];
    __shared__ __align__(16) float Bs[16][132];

    const int tid = threadIdx.x;
    const int tx = tid & 15, ty = tid >> 4;
    const int m0 = blockIdx.x * 128;
    const int n0 = blockIdx.y * 128;
    const int z  = blockIdx.z;

    const float* Ap = A;
    const float* Bp = Bsrc;
    const float* biasp = bias;
    if (MODE == 1) {
        Ap += (size_t)z * Hn;
        Bp += (size_t)z * G4 * Hn;
        biasp += (size_t)z * G4;
    }

    unsigned long long acc[4][8];
    #pragma unroll
    for (int p = 0; p < 4; p++)
        #pragma unroll
        for (int j = 0; j < 8; j++) acc[p][j] = 0ull;

    for (int k0 = 0; k0 < 128; k0 += 16) {
        // A tile: 128 m x 16 k, stored transposed As[k][m]
        #pragma unroll
        for (int jj = 0; jj < 2; jj++) {
            int lin = tid + jj * 256;            // float4 index, 512 total
            int row = lin >> 2, c4 = lin & 3;
            float4 v = *reinterpret_cast<const float4*>(
                Ap + (size_t)(m0 + row) * lda + k0 + c4 * 4);
            As[c4 * 4 + 0][row] = v.x;
            As[c4 * 4 + 1][row] = v.y;
            As[c4 * 4 + 2][row] = v.z;
            As[c4 * 4 + 3][row] = v.w;
        }
        // B tile: 128 n x 16 k from row-major weights, stored Bs[k][n]
        // NOTE: permutation must use the GLOBAL column index (n0 + n).
        #pragma unroll
        for (int jj = 0; jj < 2; jj++) {
            int lin = tid + jj * 256;
            int n = lin >> 2, c4 = lin & 3;
            int ng = n0 + n;
            int nsrc = (MODE == 1) ? ((ng & 3) * 128 + (ng >> 2)) : ng;
            float4 v = *reinterpret_cast<const float4*>(
                Bp + (size_t)nsrc * 128 + k0 + c4 * 4);
            Bs[c4 * 4 + 0][n] = v.x;
            Bs[c4 * 4 + 1][n] = v.y;
            Bs[c4 * 4 + 2][n] = v.z;
            Bs[c4 * 4 + 3][n] = v.w;
        }
        __syncthreads();
        #pragma unroll
        for (int k = 0; k < 16; k++) {
            ulonglong2 a0 = *reinterpret_cast<const ulonglong2*>(&As[k][ty * 8]);
            ulonglong2 a1 = *reinterpret_cast<const ulonglong2*>(&As[k][ty * 8 + 4]);
            float4 b0 = *reinterpret_cast<const float4*>(&Bs[k][tx * 8]);
            float4 b1 = *reinterpret_cast<const float4*>(&Bs[k][tx * 8 + 4]);
            unsigned long long ap[4] = {a0.x, a0.y, a1.x, a1.y};
            unsigned long long bb[8] = {packf2(b0.x), packf2(b0.y), packf2(b0.z), packf2(b0.w),
                                        packf2(b1.x), packf2(b1.y), packf2(b1.z), packf2(b1.w)};
            #pragma unroll
            for (int p = 0; p < 4; p++)
                #pragma unroll
                for (int j = 0; j < 8; j++) fma2(acc[p][j], ap[p], bb[j]);
        }
        __syncthreads();
    }

    // unpack pairs -> vals[8 m][8 n]
    float vals[8][8];
    #pragma unroll
    for (int p = 0; p < 4; p++)
        #pragma unroll
        for (int j = 0; j < 8; j++) {
            float2 f = unpk(acc[p][j]);
            vals[2 * p + 0][j] = f.x;
            vals[2 * p + 1][j] = f.y;
        }

    if (MODE == 0) {
        #pragma unroll
        for (int r = 0; r < 8; r++) {
            size_t m = m0 + ty * 8 + r;
            #pragma unroll
            for (int j4 = 0; j4 < 8; j4 += 4) {
                int n = n0 + tx * 8 + j4;
                float4 cvv = *reinterpret_cast<const float4*>(extra + m * 128 + n);
                float4 o;
                o.x = vals[r][j4 + 0] + bias[n + 0] + cvv.x;
                o.y = vals[r][j4 + 1] + bias[n + 1] + cvv.y;
                o.z = vals[r][j4 + 2] + bias[n + 2] + cvv.z;
                o.w = vals[r][j4 + 3] + bias[n + 3] + cvv.w;
                *reinterpret_cast<float4*>(C + m * 128 + n) = o;
            }
        }
    } else if (MODE == 1) {
        int nb = n0 + tx * 8;
        int hbase = nb >> 2;                    // 2 h values per thread
        float c0v[2] = {extra[z * Hn + hbase], extra[z * Hn + hbase + 1]};
        float bsv[8];
        #pragma unroll
        for (int j = 0; j < 8; j++) bsv[j] = biasp[nb + j];
        #pragma unroll
        for (int r = 0; r < 8; r++) {
            int b = m0 + ty * 8 + r;
            size_t off = (size_t)b * (An * Hn) + z * Hn;
            #pragma unroll
            for (int hg = 0; hg < 2; hg++) {
                float ig = vals[r][hg * 4 + 0] + bsv[hg * 4 + 0];
                float fg = vals[r][hg * 4 + 1] + bsv[hg * 4 + 1];
                float gg = vals[r][hg * 4 + 2] + bsv[hg * 4 + 2];
                float og = vals[r][hg * 4 + 3] + bsv[hg * 4 + 3];
                float c1 = sigf(fg) * c0v[hg] + sigf(ig) * tanhf(gg);
                float h1 = sigf(og) * tanhf(c1);
                C[off + hbase + hg] = h1;
                out2[off + hbase + hg] = c1;
            }
        }
    } else {  // MODE 2: bias + row softmax (n0 == 0, full 128-wide row)
        #pragma unroll
        for (int r = 0; r < 8; r++) {
            float v[8];
            #pragma unroll
            for (int j = 0; j < 8; j++) v[j] = vals[r][j] + bias[tx * 8 + j];
            float mx = v[0];
            #pragma unroll
            for (int j = 1; j < 8; j++) mx = fmaxf(mx, v[j]);
            #pragma unroll
            for (int o = 1; o < 16; o <<= 1)
                mx = fmaxf(mx, __shfl_xor_sync(0xFFFFFFFFu, mx, o));
            float s = 0.f;
            #pragma unroll
            for (int j = 0; j < 8; j++) { v[j] = expf(v[j] - mx); s += v[j]; }
            #pragma unroll
            for (int o = 1; o < 16; o <<= 1)
                s += __shfl_xor_sync(0xFFFFFFFFu, s, o);
            float inv = 1.0f / s;
            size_t m = m0 + ty * 8 + r;
            #pragma unroll
            for (int j4 = 0; j4 < 8; j4 += 4) {
                float4 o4;
                o4.x = v[j4 + 0] * inv; o4.y = v[j4 + 1] * inv;
                o4.z = v[j4 + 2] * inv; o4.w = v[j4 + 3] * inv;
                *reinterpret_cast<float4*>(C + m * 128 + tx * 8 + j4) = o4;
            }
        }
    }
}

// -------------------- comm gate: per-agent global argmax --------------------
__global__ void k_init_argmax() {
    if (threadIdx.x < An) g_argmax[threadIdx.x] = 0ull;
}

__global__ void k_argmax(const float* __restrict__ h1, const float* __restrict__ Wg,
                         const float* __restrict__ bg) {
    int w = (blockIdx.x * blockDim.x + threadIdx.x) >> 5;   // pair index b*A+a
    int lane = threadIdx.x & 31;
    if (w >= M_BIG) return;
    int b = w / An, a = w % An;
    float4 hv = *reinterpret_cast<const float4*>(h1 + (size_t)w * Hn + lane * 4);
    const float* wg = Wg + a * 2 * Hn;
    float4 g0 = *reinterpret_cast<const float4*>(wg + lane * 4);
    float4 g1 = *reinterpret_cast<const float4*>(wg + Hn + lane * 4);
    float l0 = hv.x * g0.x + hv.y * g0.y + hv.z * g0.z + hv.w * g0.w;
    float l1 = hv.x * g1.x + hv.y * g1.y + hv.z * g1.z + hv.w * g1.w;
    #pragma unroll
    for (int off = 16; off; off >>= 1) {
        l0 += __shfl_xor_sync(0xFFFFFFFFu, l0, off);
        l1 += __shfl_xor_sync(0xFFFFFFFFu, l1, off);
    }
    if (lane == 0) {
        l0 += bg[a * 2 + 0];
        l1 += bg[a * 2 + 1];
        float mm = fmaxf(l0, l1);
        float e0 = expf(l0 - mm), e1 = expf(l1 - mm);
        float s = e0 + e1;
        float p0 = e0 / s, p1 = e1 / s;
        float key; unsigned pidx;
        if (p0 >= p1) { key = p0; pidx = (unsigned)(2 * b); }
        else          { key = p1; pidx = (unsigned)(2 * b + 1); }
        unsigned long long packed =
            ((unsigned long long)__float_as_uint(key) << 32) | (0xFFFFFFFFu - pidx);
        atomicMax(&g_argmax[a], packed);
    }
}

// -------------------- build x = comm_sum - idx*h1 --------------------
__global__ __launch_bounds__(256)
void k_build_x(const float* __restrict__ h1, float* __restrict__ x,
               const int* __restrict__ alive) {
    __shared__ __align__(16) float sh[An][Hn];
    __shared__ float sidx[An];
    __shared__ float scs[Hn];
    int b = blockIdx.x;
    int tid = threadIdx.x;
    const float* hp = h1 + (size_t)b * An * Hn;
    #pragma unroll
    for (int jj = 0; jj < 4; jj++) {
        int lin = tid + jj * 256;
        int a = lin >> 5, c4 = lin & 31;
        *reinterpret_cast<float4*>(&sh[a][c4 * 4]) =
            *reinterpret_cast<const float4*>(hp + (size_t)lin * 4);
    }
    if (tid < An)
        sidx[tid] = (float)(0xFFFFFFFFu - (unsigned)(g_argmax[tid] & 0xFFFFFFFFull));
    __syncthreads();
    if (tid < Hn) {
        int v = alive ? *alive : An;
        if (v < 0 || v > (1 << 20)) v = (int)__int_as_float(v);
        float norm = v ? 1.0f / (float)(v - 1) : 1.0f;
        float sum = 0.f;
        #pragma unroll
        for (int a = 0; a < An; a++) sum += sidx[a] * sh[a][tid];
        scs[tid] = norm * sum;
    }
    __syncthreads();
    float* xp = x + (size_t)b * An * Hn;
    #pragma unroll
    for (int jj = 0; jj < 4; jj++) {
        int lin = tid + jj * 256;
        int a = lin >> 5, c4 = lin & 31;
        float4 hv = *reinterpret_cast<float4*>(&sh[a][c4 * 4]);
        float ia = sidx[a];
        float4 o;
        o.x = scs[c4 * 4 + 0] - ia * hv.x;
        o.y = scs[c4 * 4 + 1] - ia * hv.y;
        o.z = scs[c4 * 4 + 2] - ia * hv.z;
        o.w = scs[c4 * 4 + 3] - ia * hv.w;
        *reinterpret_cast<float4*>(xp + (size_t)lin * 4) = o;
    }
}

// -------------------- launch --------------------
extern "C" void kernel_launch(void* const* d_in, const int* in_sizes, int n_in,
                              void* d_out, int out_size) {
    const float* obs = (const float*)d_in[0];
    const float* cv  = (const float*)d_in[1];
    const float* h0  = (const float*)d_in[2];
    const float* c0  = (const float*)d_in[3];
    const float* We  = (const float*)d_in[4];
    const float* be  = (const float*)d_in[5];
    const float* Wih = (const float*)d_in[6];
    const float* Whh = (const float*)d_in[7];
    const float* bih = (const float*)d_in[8];
    const float* bhh = (const float*)d_in[9];
    const float* Wg  = (const float*)d_in[10];
    const float* bg  = (const float*)d_in[11];
    const float* Wt  = (const float*)d_in[12];
    const float* bt  = (const float*)d_in[13];
    const int* alive = (n_in > 14) ? (const int*)d_in[14] : nullptr;
    float* dout = (float*)d_out;

    float *p_buf1, *p_hh;
    cudaGetSymbolAddress((void**)&p_buf1, g_buf1);
    cudaGetSymbolAddress((void**)&p_hh, g_hh);

    // interleaved hidden-side bias
    k_hh<<<2048, 256>>>(h0, Whh, bih, bhh);

    // enc = obs @ We^T + be + cv  -> g_buf1
    gemm_k<0><<<dim3(M_BIG / 128, 1, 1), 256>>>(obs, We, p_buf1, Sn, be, cv, nullptr);

    // gates GEMM + fused LSTM cell -> h1 (dout+BAH), c1 (dout+2BAH)
    gemm_k<1><<<dim3(Bn / 128, 4, An), 256>>>(p_buf1, Wih, dout + BAH, An * Hn,
                                              p_hh, c0, dout + 2 * BAH);

    // comm gate argmax
    k_init_argmax<<<1, 32>>>();
    k_argmax<<<M_BIG / 8, 256>>>(dout + BAH, Wg, bg);

    // x = comm_sum - idx*h1 -> g_buf1 (reuses enc)
    k_build_x<<<Bn, 256>>>(dout + BAH, p_buf1, alive);

    // out = softmax(x @ Wt^T + bt) -> d_out
    gemm_k<2><<<dim3(M_BIG / 128, 1, 1), 256>>>(p_buf1, Wt, dout, Hn, bt, nullptr, nullptr);
}

// round 5
// speedup vs baseline: 1.9728x; 1.6199x over previous
#include <cuda_runtime.h>
#include <cuda_bf16.h>
#include <math.h>
#include <stdint.h>

// Problem constants
constexpr int Bn = 4096;
constexpr int An = 32;
constexpr int Hn = 128;
constexpr int G4 = 4 * Hn;          // 512
constexpr int M_BIG = Bn * An;      // 131072
constexpr int BAH = Bn * An * Hn;   // 16,777,216

// -------------------- scratch --------------------
__device__ float g_buf1[BAH];                  // enc, later x (67 MB)
__device__ float g_hh[An * G4];                // interleaved (4h+gate) hidden bias
__device__ unsigned long long g_argmax[An];

// ==================== helpers ====================
__device__ __forceinline__ uint32_t smem_u32(const void* p) {
    uint32_t a;
    asm("{ .reg .u64 t; cvta.to.shared.u64 t, %1; cvt.u32.u64 %0, t; }"
        : "=r"(a) : "l"(p));
    return a;
}
// pack (k_even, k_odd) -> bf16x2 with k_even in low half
__device__ __forceinline__ uint32_t pk(float k0, float k1) {
    uint32_t r;
    asm("cvt.rn.satfinite.bf16x2.f32 %0, %1, %2;" : "=r"(r) : "f"(k1), "f"(k0));
    return r;
}
__device__ __forceinline__ void ldsm_x4(uint32_t* r, uint32_t addr) {
    asm volatile("ldmatrix.sync.aligned.m8n8.x4.shared.b16 {%0,%1,%2,%3}, [%4];"
                 : "=r"(r[0]), "=r"(r[1]), "=r"(r[2]), "=r"(r[3]) : "r"(addr));
}
__device__ __forceinline__ void ldsm_x2(uint32_t* r, uint32_t addr) {
    asm volatile("ldmatrix.sync.aligned.m8n8.x2.shared.b16 {%0,%1}, [%2];"
                 : "=r"(r[0]), "=r"(r[1]) : "r"(addr));
}
__device__ __forceinline__ void mma_bf16(float* d, const uint32_t* a, const uint32_t* b) {
    asm volatile(
        "mma.sync.aligned.m16n8k16.row.col.f32.bf16.bf16.f32 "
        "{%0,%1,%2,%3}, {%4,%5,%6,%7}, {%8,%9}, {%0,%1,%2,%3};"
        : "+f"(d[0]), "+f"(d[1]), "+f"(d[2]), "+f"(d[3])
        : "r"(a[0]), "r"(a[1]), "r"(a[2]), "r"(a[3]), "r"(b[0]), "r"(b[1]));
}
__device__ __forceinline__ float fsig(float x) { return 1.0f / (1.0f + expf(-x)); }

// -------------------- SMEM layout --------------------
// operand tiles (128 rows x 64 k bf16, 128B/row, xor-swizzled 16B units)
constexpr int OF_AH = 0;
constexpr int OF_AL = 16384;
constexpr int OF_BH = 32768;
constexpr int OF_BL = 49152;           // tiles end 65536
// stage (float[128][132]) aliases tiles (67584 B)
constexpr int OF_MISC = 69632;         // s_bias[128], s_c0[32]
constexpr int SMEM_SZ = 70912;

// swizzled byte offset of 16B unit: row in [0,128), u = k8-unit in [0,8)
__device__ __forceinline__ uint32_t su(int row, int u) {
    return (uint32_t)(row * 128 + ((u ^ (row & 7)) << 4));
}

// ==================== fused bf16-split GEMM ====================
// C[m][n] = sum_k A[m][k]*B[n][k], M=128/block, N=128, K=128.
// MODE 0: enc = obs@We^T + be + cv            grid(1024)        lda=128
// MODE 1: gates chunk -> LSTM -> h1, c1       grid(32, 4, 32)   lda=4096
//         (B rows permuted: interleaved col ng=nc*128+n -> src row (ng&3)*128+(ng>>2))
// MODE 2: out = softmax(x@Wt^T + bt)          grid(1024)        lda=128
template <int MODE>
__global__ __launch_bounds__(256, 2)
void tc_gemm(const float* __restrict__ A, const float* __restrict__ Bsrc,
             float* __restrict__ C, float* __restrict__ C2,
             const float* __restrict__ bias, const float* __restrict__ cv,
             const float* __restrict__ c0)
{
    extern __shared__ char sm[];
    float* stage = (float*)sm;                  // aliases tiles
    float* s_bias = (float*)(sm + OF_MISC);     // 128
    float* s_c0 = s_bias + 128;                 // 32

    const int tid = threadIdx.x;
    const int wid = tid >> 5, lane = tid & 31;
    const int m0 = blockIdx.x * 128;
    const int nc = (MODE == 1) ? blockIdx.y : 0;
    const int z  = (MODE == 1) ? blockIdx.z : 0;
    const uint32_t sb = smem_u32(sm);

    const int lda = (MODE == 1) ? (An * Hn) : Hn;
    const float* Ap = A + (MODE == 1 ? (size_t)z * Hn : 0);
    const float* Bp = Bsrc + (MODE == 1 ? (size_t)z * G4 * Hn : 0);

    if (MODE == 1) {
        if (tid < 128) s_bias[tid] = g_hh[z * G4 + nc * 128 + tid];
        if (tid < 32)  s_c0[tid] = c0[z * Hn + nc * 32 + tid];
    }

    // warp tiling: 4 m-warps x 2 n-warps; warp tile 32(m) x 64(n)
    const int wm = (wid & 3) * 32;
    const int wn = (wid >> 2) * 64;

    float acc[2][8][4];
    #pragma unroll
    for (int mt = 0; mt < 2; mt++)
        #pragma unroll
        for (int nt = 0; nt < 8; nt++)
            #pragma unroll
            for (int e = 0; e < 4; e++) acc[mt][nt][e] = 0.f;

    for (int kc = 0; kc < 2; kc++) {
        const int k0 = kc * 64;
        // ---- load A,B tiles: 128 rows x 64 k each, split hi/lo bf16 ----
        #pragma unroll
        for (int i = 0; i < 4; i++) {
            int idx = tid + i * 256;          // 1024: row(128) x unit(8)
            int row = idx >> 3, u = idx & 7;
            {   // A
                const float* p = Ap + (size_t)(m0 + row) * lda + k0 + u * 8;
                float4 v0 = *reinterpret_cast<const float4*>(p);
                float4 v1 = *reinterpret_cast<const float4*>(p + 4);
                float h0 = __bfloat162float(__float2bfloat16(v0.x));
                float h1 = __bfloat162float(__float2bfloat16(v0.y));
                float h2 = __bfloat162float(__float2bfloat16(v0.z));
                float h3 = __bfloat162float(__float2bfloat16(v0.w));
                float h4 = __bfloat162float(__float2bfloat16(v1.x));
                float h5 = __bfloat162float(__float2bfloat16(v1.y));
                float h6 = __bfloat162float(__float2bfloat16(v1.z));
                float h7 = __bfloat162float(__float2bfloat16(v1.w));
                uint4 hi = make_uint4(pk(v0.x, v0.y), pk(v0.z, v0.w),
                                      pk(v1.x, v1.y), pk(v1.z, v1.w));
                uint4 lo = make_uint4(pk(v0.x - h0, v0.y - h1), pk(v0.z - h2, v0.w - h3),
                                      pk(v1.x - h4, v1.y - h5), pk(v1.z - h6, v1.w - h7));
                uint32_t off = su(row, u);
                *reinterpret_cast<uint4*>(sm + OF_AH + off) = hi;
                *reinterpret_cast<uint4*>(sm + OF_AL + off) = lo;
            }
            {   // B (optionally permuted rows for gate interleave)
                int srow = row;
                if (MODE == 1) {
                    int ng = nc * 128 + row;
                    srow = (ng & 3) * 128 + (ng >> 2);
                }
                const float* p = Bp + (size_t)srow * Hn + k0 + u * 8;
                float4 v0 = *reinterpret_cast<const float4*>(p);
                float4 v1 = *reinterpret_cast<const float4*>(p + 4);
                float h0 = __bfloat162float(__float2bfloat16(v0.x));
                float h1 = __bfloat162float(__float2bfloat16(v0.y));
                float h2 = __bfloat162float(__float2bfloat16(v0.z));
                float h3 = __bfloat162float(__float2bfloat16(v0.w));
                float h4 = __bfloat162float(__float2bfloat16(v1.x));
                float h5 = __bfloat162float(__float2bfloat16(v1.y));
                float h6 = __bfloat162float(__float2bfloat16(v1.z));
                float h7 = __bfloat162float(__float2bfloat16(v1.w));
                uint4 hi = make_uint4(pk(v0.x, v0.y), pk(v0.z, v0.w),
                                      pk(v1.x, v1.y), pk(v1.z, v1.w));
                uint4 lo = make_uint4(pk(v0.x - h0, v0.y - h1), pk(v0.z - h2, v0.w - h3),
                                      pk(v1.x - h4, v1.y - h5), pk(v1.z - h6, v1.w - h7));
                uint32_t off = su(row, u);
                *reinterpret_cast<uint4*>(sm + OF_BH + off) = hi;
                *reinterpret_cast<uint4*>(sm + OF_BL + off) = lo;
            }
        }
        __syncthreads();

        // ---- MMA: 4 k16 steps x 3 split passes ----
        // lane-specific fragment addresses
        const int arow = (lane & 7) + ((lane >> 3) & 1) * 8;   // row within m16 tile
        const int akq  = lane >> 4;                            // k8 half
        const int bl   = lane & 15;
        const int brow = bl & 7;
        const int bkq  = (bl >> 3) & 1;

        #pragma unroll
        for (int ks = 0; ks < 4; ks++) {
            uint32_t a[2][4], b[8][2];
            // A_hi x B_hi
            #pragma unroll
            for (int mt = 0; mt < 2; mt++)
                ldsm_x4(a[mt], sb + OF_AH + su(wm + mt * 16 + arow, ks * 2 + akq));
            #pragma unroll
            for (int nt = 0; nt < 8; nt++)
                ldsm_x2(b[nt], sb + OF_BH + su(wn + nt * 8 + brow, ks * 2 + bkq));
            #pragma unroll
            for (int mt = 0; mt < 2; mt++)
                #pragma unroll
                for (int nt = 0; nt < 8; nt++) mma_bf16(acc[mt][nt], a[mt], b[nt]);
            // A_lo x B_hi
            #pragma unroll
            for (int mt = 0; mt < 2; mt++)
                ldsm_x4(a[mt], sb + OF_AL + su(wm + mt * 16 + arow, ks * 2 + akq));
            #pragma unroll
            for (int mt = 0; mt < 2; mt++)
                #pragma unroll
                for (int nt = 0; nt < 8; nt++) mma_bf16(acc[mt][nt], a[mt], b[nt]);
            // A_hi x B_lo
            #pragma unroll
            for (int mt = 0; mt < 2; mt++)
                ldsm_x4(a[mt], sb + OF_AH + su(wm + mt * 16 + arow, ks * 2 + akq));
            #pragma unroll
            for (int nt = 0; nt < 8; nt++)
                ldsm_x2(b[nt], sb + OF_BL + su(wn + nt * 8 + brow, ks * 2 + bkq));
            #pragma unroll
            for (int mt = 0; mt < 2; mt++)
                #pragma unroll
                for (int nt = 0; nt < 8; nt++) mma_bf16(acc[mt][nt], a[mt], b[nt]);
        }
        __syncthreads();
    }

    // ---- stage C tile in SMEM (aliases operand tiles; synced above) ----
    {
        const int grp = lane >> 2, qp = lane & 3;
        #pragma unroll
        for (int mt = 0; mt < 2; mt++)
            #pragma unroll
            for (int nt = 0; nt < 8; nt++) {
                int r = wm + mt * 16 + grp;
                int c = wn + nt * 8 + qp * 2;
                stage[r * 132 + c] = acc[mt][nt][0];
                stage[r * 132 + c + 1] = acc[mt][nt][1];
                stage[(r + 8) * 132 + c] = acc[mt][nt][2];
                stage[(r + 8) * 132 + c + 1] = acc[mt][nt][3];
            }
    }
    __syncthreads();

    // ---- epilogues ----
    if (MODE == 0) {
        #pragma unroll
        for (int i = 0; i < 16; i++) {
            int task = tid + i * 256;         // 4096 float4 tasks
            int r = task >> 5, cq = (task & 31) * 4;
            size_t m = m0 + r;
            float4 bv = *reinterpret_cast<const float4*>(bias + cq);
            float4 cvv = *reinterpret_cast<const float4*>(cv + m * 128 + cq);
            float4 o;
            o.x = stage[r * 132 + cq + 0] + bv.x + cvv.x;
            o.y = stage[r * 132 + cq + 1] + bv.y + cvv.y;
            o.z = stage[r * 132 + cq + 2] + bv.z + cvv.z;
            o.w = stage[r * 132 + cq + 3] + bv.w + cvv.w;
            *reinterpret_cast<float4*>(C + m * 128 + cq) = o;
        }
    } else if (MODE == 1) {
        #pragma unroll
        for (int i = 0; i < 16; i++) {
            int task = tid + i * 256;         // 4096: (r, hl)
            int r = task >> 5, hl = task & 31;
            float ig = stage[r * 132 + 4 * hl + 0] + s_bias[4 * hl + 0];
            float fg = stage[r * 132 + 4 * hl + 1] + s_bias[4 * hl + 1];
            float gg = stage[r * 132 + 4 * hl + 2] + s_bias[4 * hl + 2];
            float og = stage[r * 132 + 4 * hl + 3] + s_bias[4 * hl + 3];
            float cc = fsig(fg) * s_c0[hl] + fsig(ig) * tanhf(gg);
            float hv = fsig(og) * tanhf(cc);
            size_t off = (size_t)(m0 + r) * (An * Hn) + z * Hn + nc * 32 + hl;
            C[off] = hv;
            C2[off] = cc;
        }
    } else {  // MODE 2: bias + row softmax, warp handles 16 rows
        #pragma unroll 1
        for (int rr = 0; rr < 16; rr++) {
            int r = wid * 16 + rr;
            float v[4];
            #pragma unroll
            for (int j = 0; j < 4; j++)
                v[j] = stage[r * 132 + lane * 4 + j] + bias[lane * 4 + j];
            float mx = fmaxf(fmaxf(v[0], v[1]), fmaxf(v[2], v[3]));
            #pragma unroll
            for (int o = 16; o; o >>= 1)
                mx = fmaxf(mx, __shfl_xor_sync(0xFFFFFFFFu, mx, o));
            float s = 0.f;
            #pragma unroll
            for (int j = 0; j < 4; j++) { v[j] = expf(v[j] - mx); s += v[j]; }
            #pragma unroll
            for (int o = 16; o; o >>= 1)
                s += __shfl_xor_sync(0xFFFFFFFFu, s, o);
            float inv = 1.0f / s;
            float4 o4 = make_float4(v[0] * inv, v[1] * inv, v[2] * inv, v[3] * inv);
            *reinterpret_cast<float4*>(C + (size_t)(m0 + r) * 128 + lane * 4) = o4;
        }
    }
}

// ==================== small kernels (round-3 proven) ====================
__global__ void k_hh(const float* __restrict__ h0, const float* __restrict__ Whh,
                     const float* __restrict__ bih, const float* __restrict__ bhh) {
    if (blockIdx.x == 0 && threadIdx.x < An) g_argmax[threadIdx.x] = 0ull;
    int w = (blockIdx.x * blockDim.x + threadIdx.x) >> 5;
    int lane = threadIdx.x & 31;
    if (w >= An * G4) return;
    int a = w / G4;
    float4 hv = *reinterpret_cast<const float4*>(h0 + a * Hn + lane * 4);
    float4 wv = *reinterpret_cast<const float4*>(Whh + (size_t)w * Hn + lane * 4);
    float s = hv.x * wv.x + hv.y * wv.y + hv.z * wv.z + hv.w * wv.w;
    #pragma unroll
    for (int off = 16; off; off >>= 1) s += __shfl_xor_sync(0xFFFFFFFFu, s, off);
    if (lane == 0) {
        int gsrc = w % G4;
        int gate = gsrc >> 7, h = gsrc & 127;
        g_hh[a * G4 + 4 * h + gate] = s + bih[w] + bhh[w];
    }
}

__global__ void k_argmax(const float* __restrict__ h1, const float* __restrict__ Wg,
                         const float* __restrict__ bg) {
    int w = (blockIdx.x * blockDim.x + threadIdx.x) >> 5;
    int lane = threadIdx.x & 31;
    if (w >= M_BIG) return;
    int b = w / An, a = w % An;
    float4 hv = *reinterpret_cast<const float4*>(h1 + (size_t)w * Hn + lane * 4);
    const float* wg = Wg + a * 2 * Hn;
    float4 g0 = *reinterpret_cast<const float4*>(wg + lane * 4);
    float4 g1 = *reinterpret_cast<const float4*>(wg + Hn + lane * 4);
    float l0 = hv.x * g0.x + hv.y * g0.y + hv.z * g0.z + hv.w * g0.w;
    float l1 = hv.x * g1.x + hv.y * g1.y + hv.z * g1.z + hv.w * g1.w;
    #pragma unroll
    for (int off = 16; off; off >>= 1) {
        l0 += __shfl_xor_sync(0xFFFFFFFFu, l0, off);
        l1 += __shfl_xor_sync(0xFFFFFFFFu, l1, off);
    }
    if (lane == 0) {
        l0 += bg[a * 2 + 0];
        l1 += bg[a * 2 + 1];
        float mm = fmaxf(l0, l1);
        float e0 = expf(l0 - mm), e1 = expf(l1 - mm);
        float s = e0 + e1;
        float p0 = e0 / s, p1 = e1 / s;
        float key; unsigned pidx;
        if (p0 >= p1) { key = p0; pidx = (unsigned)(2 * b); }
        else          { key = p1; pidx = (unsigned)(2 * b + 1); }
        unsigned long long packed =
            ((unsigned long long)__float_as_uint(key) << 32) | (0xFFFFFFFFu - pidx);
        atomicMax(&g_argmax[a], packed);
    }
}

__global__ __launch_bounds__(256)
void k_build_x(const float* __restrict__ h1, float* __restrict__ x,
               const int* __restrict__ alive) {
    __shared__ __align__(16) float sh[An][Hn];
    __shared__ float sidx[An];
    __shared__ float scs[Hn];
    int b = blockIdx.x;
    int tid = threadIdx.x;
    const float* hp = h1 + (size_t)b * An * Hn;
    #pragma unroll
    for (int jj = 0; jj < 4; jj++) {
        int lin = tid + jj * 256;
        int a = lin >> 5, c4 = lin & 31;
        *reinterpret_cast<float4*>(&sh[a][c4 * 4]) =
            *reinterpret_cast<const float4*>(hp + (size_t)lin * 4);
    }
    if (tid < An)
        sidx[tid] = (float)(0xFFFFFFFFu - (unsigned)(g_argmax[tid] & 0xFFFFFFFFull));
    __syncthreads();
    if (tid < Hn) {
        int v = alive ? *alive : An;
        if (v < 0 || v > (1 << 20)) v = (int)__int_as_float(v);
        float norm = v ? 1.0f / (float)(v - 1) : 1.0f;
        float sum = 0.f;
        #pragma unroll
        for (int a = 0; a < An; a++) sum += sidx[a] * sh[a][tid];
        scs[tid] = norm * sum;
    }
    __syncthreads();
    float* xp = x + (size_t)b * An * Hn;
    #pragma unroll
    for (int jj = 0; jj < 4; jj++) {
        int lin = tid + jj * 256;
        int a = lin >> 5, c4 = lin & 31;
        float4 hv = *reinterpret_cast<float4*>(&sh[a][c4 * 4]);
        float ia = sidx[a];
        float4 o;
        o.x = scs[c4 * 4 + 0] - ia * hv.x;
        o.y = scs[c4 * 4 + 1] - ia * hv.y;
        o.z = scs[c4 * 4 + 2] - ia * hv.z;
        o.w = scs[c4 * 4 + 3] - ia * hv.w;
        *reinterpret_cast<float4*>(xp + (size_t)lin * 4) = o;
    }
}

// ==================== launch ====================
extern "C" void kernel_launch(void* const* d_in, const int* in_sizes, int n_in,
                              void* d_out, int out_size) {
    const float* obs = (const float*)d_in[0];
    const float* cv  = (const float*)d_in[1];
    const float* h0  = (const float*)d_in[2];
    const float* c0  = (const float*)d_in[3];
    const float* We  = (const float*)d_in[4];
    const float* be  = (const float*)d_in[5];
    const float* Wih = (const float*)d_in[6];
    const float* Whh = (const float*)d_in[7];
    const float* bih = (const float*)d_in[8];
    const float* bhh = (const float*)d_in[9];
    const float* Wg  = (const float*)d_in[10];
    const float* bg  = (const float*)d_in[11];
    const float* Wt  = (const float*)d_in[12];
    const float* bt  = (const float*)d_in[13];
    const int* alive = (n_in > 14) ? (const int*)d_in[14] : nullptr;
    float* dout = (float*)d_out;

    float* p_buf1;
    cudaGetSymbolAddress((void**)&p_buf1, g_buf1);

    cudaFuncSetAttribute(tc_gemm<0>, cudaFuncAttributeMaxDynamicSharedMemorySize, SMEM_SZ);
    cudaFuncSetAttribute(tc_gemm<1>, cudaFuncAttributeMaxDynamicSharedMemorySize, SMEM_SZ);
    cudaFuncSetAttribute(tc_gemm<2>, cudaFuncAttributeMaxDynamicSharedMemorySize, SMEM_SZ);

    // interleaved hidden-side bias (+ argmax init)
    k_hh<<<2048, 256>>>(h0, Whh, bih, bhh);

    // enc = obs @ We^T + be + cv -> g_buf1
    tc_gemm<0><<<dim3(M_BIG / 128, 1, 1), 256, SMEM_SZ>>>(
        obs, We, p_buf1, nullptr, be, cv, nullptr);

    // gates + LSTM -> h1 (dout+BAH), c1 (dout+2BAH)
    tc_gemm<1><<<dim3(Bn / 128, 4, An), 256, SMEM_SZ>>>(
        p_buf1, Wih, dout + BAH, dout + 2 * BAH, nullptr, nullptr, c0);

    // comm-gate argmax
    k_argmax<<<M_BIG / 8, 256>>>(dout + BAH, Wg, bg);

    // x = comm_sum - idx*h1 -> g_buf1
    k_build_x<<<Bn, 256>>>(dout + BAH, p_buf1, alive);

    // out = softmax(x @ Wt^T + bt) -> dout
    tc_gemm<2><<<dim3(M_BIG / 128, 1, 1), 256, SMEM_SZ>>>(
        p_buf1, Wt, dout, nullptr, bt, nullptr, nullptr);
}